// round 7
// baseline (speedup 1.0000x reference)
#include <cuda_runtime.h>

#define BB 256
#define TT 2048
#define II 128
#define HH 256
#define AA 8

typedef unsigned long long ull;

// 512MB scratch for xproj[b][t][h]
__device__ float g_xproj[(size_t)BB * TT * HH];

__device__ __forceinline__ ull ffma2(ull a, ull b, ull c) {
  ull d;
  asm("fma.rn.f32x2 %0, %1, %2, %3;" : "=l"(d) : "l"(a), "l"(b), "l"(c));
  return d;
}
__device__ __forceinline__ ull add2(ull a, ull b) {
  ull d;
  asm("add.rn.f32x2 %0, %1, %2;" : "=l"(d) : "l"(a), "l"(b));
  return d;
}
__device__ __forceinline__ ull pack2(float lo, float hi) {
  ull d;
  asm("mov.b64 %0, {%1, %2};" : "=l"(d) : "f"(lo), "f"(hi));
  return d;
}
__device__ __forceinline__ float hsum2(ull v) {
  float lo, hi;
  asm("mov.b64 {%0, %1}, %2;" : "=f"(lo), "=f"(hi) : "l"(v));
  return lo + hi;
}
__device__ __forceinline__ void unpack2(ull v, float& lo, float& hi) {
  asm("mov.b64 {%0, %1}, %2;" : "=f"(lo), "=f"(hi) : "l"(v));
}

// ---------------------------------------------------------------------------
// Kernel 1: xproj[r][j] = sum_k x[r][k] * W_ih[j][k]
// 512 threads: thread = (jp = tid>>2 -> j in {2jp, 2jp+1}, kh = tid&3 ->
// k window [32kh, 32kh+32)). W in 32 ull regs. Chunks of 4 x-rows staged in
// double-buffered smem; each LDS.128 broadcast feeds 4 FFMA2 (fma-bound).
// kh-quartet reduce-scatter via 3 x 64-bit shfl_xor; lane kh owns row kh.
// ---------------------------------------------------------------------------
__global__ void __launch_bounds__(512) xproj_kernel(
    const float* __restrict__ x, const float* __restrict__ W_ih) {
  __shared__ float sX[2][512];

  const int tid = threadIdx.x;
  const int kh = tid & 3;
  const int jp = tid >> 2;  // 0..127
  const int j0 = 2 * jp;

  // W regs: 2 j x 32 k = 16 ull each
  ull w0[16], w1[16];
  {
    const float4* wp0 =
        reinterpret_cast<const float4*>(W_ih + j0 * II + kh * 32);
    const float4* wp1 =
        reinterpret_cast<const float4*>(W_ih + (j0 + 1) * II + kh * 32);
    #pragma unroll
    for (int i = 0; i < 8; ++i) {
      float4 f0 = __ldg(wp0 + i);
      float4 f1 = __ldg(wp1 + i);
      w0[2 * i]     = pack2(f0.x, f0.y);
      w0[2 * i + 1] = pack2(f0.z, f0.w);
      w1[2 * i]     = pack2(f1.x, f1.y);
      w1[2 * i + 1] = pack2(f1.z, f1.w);
    }
  }

  const size_t rowbase = (size_t)blockIdx.x * 256;
  const float4* xg4 = reinterpret_cast<const float4*>(x + rowbase * II);

  if (tid < 128) {
    reinterpret_cast<float4*>(sX[0])[tid] = __ldg(xg4 + tid);
  }
  __syncthreads();

  for (int c = 0; c < 64; ++c) {
    float4 pf;
    if (c < 63 && tid < 128) pf = __ldg(xg4 + (c + 1) * 128 + tid);

    const float* cur = sX[c & 1];
    ull acc[4][2];
    #pragma unroll
    for (int r = 0; r < 4; ++r) { acc[r][0] = 0ull; acc[r][1] = 0ull; }

    #pragma unroll
    for (int r = 0; r < 4; ++r) {
      const ulonglong2* xr =
          reinterpret_cast<const ulonglong2*>(cur + r * II + kh * 32);
      #pragma unroll
      for (int q = 0; q < 8; ++q) {
        ulonglong2 xv = xr[q];
        acc[r][0] = ffma2(w0[2 * q],     xv.x, acc[r][0]);
        acc[r][0] = ffma2(w0[2 * q + 1], xv.y, acc[r][0]);
        acc[r][1] = ffma2(w1[2 * q],     xv.x, acc[r][1]);
        acc[r][1] = ffma2(w1[2 * q + 1], xv.y, acc[r][1]);
      }
    }

    if (c < 63 && tid < 128) {
      reinterpret_cast<float4*>(sX[(c + 1) & 1])[tid] = pf;
    }

    // pack per-row (jsel0, jsel1) sums
    ull itm[4];
    #pragma unroll
    for (int r = 0; r < 4; ++r) {
      itm[r] = pack2(hsum2(acc[r][0]), hsum2(acc[r][1]));
    }

    // reduce-scatter over the kh quartet (lane bits 0,1)
    const bool s0 = (tid & 1), s1 = (tid & 2);
    ull k0 = s0 ? itm[1] : itm[0];
    ull k1 = s0 ? itm[3] : itm[2];
    ull g0 = s0 ? itm[0] : itm[1];
    ull g1 = s0 ? itm[2] : itm[3];
    k0 = add2(k0, __shfl_xor_sync(0xffffffffu, g0, 1));
    k1 = add2(k1, __shfl_xor_sync(0xffffffffu, g1, 1));
    ull kk = s1 ? k1 : k0;
    ull gg = s1 ? k0 : k1;
    kk = add2(kk, __shfl_xor_sync(0xffffffffu, gg, 2));

    float r0, r1;
    unpack2(kk, r0, r1);
    float* op = g_xproj + (rowbase + (size_t)c * 4 + kh) * HH + j0;
    *reinterpret_cast<float2*>(op) = make_float2(r0, r1);

    __syncthreads();
  }
}

// ---------------------------------------------------------------------------
// Kernel 2: recurrence. 128 CTAs x 512 threads, one CTA per batch pair.
// Thread (JQ = tid>>3, KH = tid&7): j in [4JQ, 4JQ+4), k in [32KH, 32KH+32).
// W: 64 floats/thread in regs (wr[4][8]) + 64 floats via conflict-free
// [e][512] LDS.128 -> NO register spill (target ~112 regs). h double-buffered
// in padded [8][36] smem. Octet reduce-scatter via shfl_xor(1,2,4); one
// barrier per step.
// ---------------------------------------------------------------------------
__global__ void __launch_bounds__(512, 1) recurrence_kernel(
    const float* __restrict__ hx, const float* __restrict__ W_hh,
    const float* __restrict__ W_actor, const float* __restrict__ W_critic,
    float* __restrict__ out) {
  extern __shared__ float smem[];
  // sW: 16 * 512 ulonglong2 = 131072B, then h buffers [2 parity][2 b][288]
  ulonglong2* sW = reinterpret_cast<ulonglong2*>(smem);
  float* shb = smem + 16 * 512 * 4;  // 32768 floats

  const int tid = threadIdx.x;
  const int JQ = tid >> 3;   // 0..63
  const int KH = tid & 7;    // 0..7
  const int jb = JQ * 4;
  const int kb = KH * 32;
  const int b0g = blockIdx.x * 2;

  const int jf = JQ * 4 + (KH & 3);  // owned j for finalize
  const int bf = KH >> 2;            // owned batch

  // ---- stage W regs: q = 0..3 (k = kb .. kb+15) ----
  ull wr[4][8];
  #pragma unroll
  for (int j = 0; j < 4; ++j) {
    const float4* wp =
        reinterpret_cast<const float4*>(W_hh + (jb + j) * HH + kb);
    #pragma unroll
    for (int q = 0; q < 4; ++q) {
      float4 f = __ldg(wp + q);
      wr[j][2 * q]     = pack2(f.x, f.y);
      wr[j][2 * q + 1] = pack2(f.z, f.w);
    }
  }
  // ---- stage W smem: q = 4..7 (k = kb+16 .. kb+31) ----
  #pragma unroll
  for (int q = 4; q < 8; ++q) {
    #pragma unroll
    for (int j = 0; j < 4; ++j) {
      float4 f = __ldg(reinterpret_cast<const float4*>(
          W_hh + (jb + j) * HH + kb) + q);
      ulonglong2 v;
      v.x = pack2(f.x, f.y);
      v.y = pack2(f.z, f.w);
      sW[((q - 4) * 4 + j) * 512 + tid] = v;
    }
  }

  // ---- init h ----
  float h_old = hx[(b0g + bf) * HH + jf];
  shb[bf * 288 + (jf >> 5) * 36 + (jf & 31)] = h_old;
  __syncthreads();

  const float* xqp = g_xproj + ((size_t)(b0g + bf) * TT) * HH + jf;
  float xq_cur = __ldg(xqp);

  for (int t = 0; t < TT; ++t) {
    const int rp = t & 1;
    float xq_nxt = 0.0f;
    if (t + 1 < TT) xq_nxt = __ldg(xqp + (size_t)(t + 1) * HH);

    const float* hbase = shb + rp * 576;
    const ulonglong2* hp0 =
        reinterpret_cast<const ulonglong2*>(hbase + KH * 36);
    const ulonglong2* hp1 =
        reinterpret_cast<const ulonglong2*>(hbase + 288 + KH * 36);

    ull a[8];
    #pragma unroll
    for (int i = 0; i < 8; ++i) a[i] = 0ull;

    #pragma unroll
    for (int q = 0; q < 8; ++q) {
      ulonglong2 v0 = hp0[q];
      ulonglong2 v1 = hp1[q];
      if (q < 4) {
        #pragma unroll
        for (int j = 0; j < 4; ++j) {
          a[j]     = ffma2(wr[j][2 * q],     v0.x, a[j]);
          a[j]     = ffma2(wr[j][2 * q + 1], v0.y, a[j]);
          a[4 + j] = ffma2(wr[j][2 * q],     v1.x, a[4 + j]);
          a[4 + j] = ffma2(wr[j][2 * q + 1], v1.y, a[4 + j]);
        }
      } else {
        #pragma unroll
        for (int j = 0; j < 4; ++j) {
          ulonglong2 wv = sW[((q - 4) * 4 + j) * 512 + tid];
          a[j]     = ffma2(wv.x, v0.x, a[j]);
          a[j]     = ffma2(wv.y, v0.y, a[j]);
          a[4 + j] = ffma2(wv.x, v1.x, a[4 + j]);
          a[4 + j] = ffma2(wv.y, v1.y, a[4 + j]);
        }
      }
    }

    // ---- octet reduce-scatter over KH bits ----
    const bool s0 = (tid & 1), s1 = (tid & 2), s2 = (tid & 4);
    ull w4[4];
    #pragma unroll
    for (int r = 0; r < 4; ++r) {
      ull keep = s0 ? a[2 * r + 1] : a[2 * r];
      ull give = s0 ? a[2 * r]     : a[2 * r + 1];
      ull recv = __shfl_xor_sync(0xffffffffu, give, 1);
      w4[r] = add2(keep, recv);
    }
    ull w2[2];
    #pragma unroll
    for (int r = 0; r < 2; ++r) {
      ull keep = s1 ? w4[2 * r + 1] : w4[2 * r];
      ull give = s1 ? w4[2 * r]     : w4[2 * r + 1];
      ull recv = __shfl_xor_sync(0xffffffffu, give, 2);
      w2[r] = add2(keep, recv);
    }
    ull keep = s2 ? w2[1] : w2[0];
    ull give = s2 ? w2[0] : w2[1];
    ull recv = __shfl_xor_sync(0xffffffffu, give, 4);
    ull tot = add2(keep, recv);

    // ---- finalize owned (b, j) ----
    float p = hsum2(tot) + xq_cur;
    h_old = 0.8f * h_old + 0.2f * fmaxf(p, 0.0f);
    shb[(rp ^ 1) * 576 + bf * 288 + (jf >> 5) * 36 + (jf & 31)] = h_old;
    xq_cur = xq_nxt;
    __syncthreads();
  }

  // -------- epilogue (final h in parity-0 buffer) --------
  const float* hf0 = shb;
  const float* hf1 = shb + 288;
  float* out_actor  = out;                 // [B][A]
  float* out_critic = out + BB * AA;       // [B]
  float* out_hx     = out + BB * AA + BB;  // [B][H]

  if (tid < HH) {
    int pj = (tid >> 5) * 36 + (tid & 31);
    out_hx[b0g * HH + tid]       = hf0[pj];
    out_hx[(b0g + 1) * HH + tid] = hf1[pj];
  }

  const int wid = tid >> 5, lane = tid & 31;
  if (wid < AA) {
    float pa0 = 0.f, pa1 = 0.f;
    for (int jj = lane; jj < HH; jj += 32) {
      int pj = (jj >> 5) * 36 + (jj & 31);
      float wa = W_actor[wid * HH + jj];
      pa0 += wa * hf0[pj];
      pa1 += wa * hf1[pj];
    }
    #pragma unroll
    for (int off = 16; off; off >>= 1) {
      pa0 += __shfl_down_sync(0xffffffffu, pa0, off);
      pa1 += __shfl_down_sync(0xffffffffu, pa1, off);
    }
    if (lane == 0) {
      out_actor[b0g * AA + wid]       = pa0;
      out_actor[(b0g + 1) * AA + wid] = pa1;
    }
  }
  if (wid == 8) {
    float pc0 = 0.f, pc1 = 0.f;
    for (int jj = lane; jj < HH; jj += 32) {
      int pj = (jj >> 5) * 36 + (jj & 31);
      float wc = W_critic[jj];
      pc0 += wc * hf0[pj];
      pc1 += wc * hf1[pj];
    }
    #pragma unroll
    for (int off = 16; off; off >>= 1) {
      pc0 += __shfl_down_sync(0xffffffffu, pc0, off);
      pc1 += __shfl_down_sync(0xffffffffu, pc1, off);
    }
    if (lane == 0) {
      out_critic[b0g]     = pc0;
      out_critic[b0g + 1] = pc1;
    }
  }
}

// ---------------------------------------------------------------------------
extern "C" void kernel_launch(void* const* d_in, const int* in_sizes, int n_in,
                              void* d_out, int out_size) {
  const float* x        = (const float*)d_in[0];
  const float* hx       = (const float*)d_in[1];
  const float* W_ih     = (const float*)d_in[2];
  const float* W_hh     = (const float*)d_in[3];
  const float* W_actor  = (const float*)d_in[4];
  const float* W_critic = (const float*)d_in[5];
  float* out = (float*)d_out;

  // smem: W 16*512*16B = 131072B + h 2*2*288*4B = 4608B
  const int smem2 = 131072 + 4608;

  cudaFuncSetAttribute(recurrence_kernel,
                       cudaFuncAttributeMaxDynamicSharedMemorySize, smem2);

  xproj_kernel<<<(BB * TT) / 256, 512>>>(x, W_ih);
  recurrence_kernel<<<BB / 2, 512, smem2>>>(hx, W_hh, W_actor, W_critic, out);
}

// round 8
// speedup vs baseline: 1.2021x; 1.2021x over previous
#include <cuda_runtime.h>

#define BB 256
#define TT 2048
#define II 128
#define HH 256
#define AA 8

typedef unsigned long long ull;

// 512MB scratch for xproj[b][t][h]
__device__ float g_xproj[(size_t)BB * TT * HH];

__device__ __forceinline__ ull ffma2(ull a, ull b, ull c) {
  ull d;
  asm("fma.rn.f32x2 %0, %1, %2, %3;" : "=l"(d) : "l"(a), "l"(b), "l"(c));
  return d;
}
__device__ __forceinline__ ull add2(ull a, ull b) {
  ull d;
  asm("add.rn.f32x2 %0, %1, %2;" : "=l"(d) : "l"(a), "l"(b));
  return d;
}
__device__ __forceinline__ ull pack2(float lo, float hi) {
  ull d;
  asm("mov.b64 %0, {%1, %2};" : "=l"(d) : "f"(lo), "f"(hi));
  return d;
}
__device__ __forceinline__ float hsum2(ull v) {
  float lo, hi;
  asm("mov.b64 {%0, %1}, %2;" : "=f"(lo), "=f"(hi) : "l"(v));
  return lo + hi;
}

// ---------------------------------------------------------------------------
// Kernel 1: xproj — the proven R6 version (512 thr, 2-way k-split, 8-row
// double-buffered chunks, one barrier per 2048-FFMA2 quantum). ~1.13 ms.
// ---------------------------------------------------------------------------
__global__ void __launch_bounds__(512) xproj_kernel(
    const float* __restrict__ x, const float* __restrict__ W_ih) {
  __shared__ float sX[2][1024];
  __shared__ float sP[2][8 * 256];

  const int tid = threadIdx.x;
  const int j = tid & 255;
  const int kh = tid >> 8;

  ull w[32];
  {
    const float2* wp =
        reinterpret_cast<const float2*>(W_ih + j * II + kh * 64);
    #pragma unroll
    for (int i = 0; i < 32; ++i) {
      float2 v = __ldg(wp + i);
      w[i] = pack2(v.x, v.y);
    }
  }

  const size_t rowbase = (size_t)blockIdx.x * 256;
  const float4* xg4 = reinterpret_cast<const float4*>(x + rowbase * II);

  if (tid < 256) {
    reinterpret_cast<float4*>(sX[0])[tid] = __ldg(xg4 + tid);
  }
  __syncthreads();

  for (int c = 0; c < 32; ++c) {
    float4 pf;
    if (c < 31 && tid < 256) pf = __ldg(xg4 + (c + 1) * 256 + tid);

    const float* cur = sX[c & 1];
    ull acc[8];
    #pragma unroll
    for (int r = 0; r < 8; ++r) acc[r] = 0ull;

    #pragma unroll
    for (int r = 0; r < 8; ++r) {
      const ulonglong2* xr =
          reinterpret_cast<const ulonglong2*>(cur + r * II + kh * 64);
      #pragma unroll
      for (int q = 0; q < 16; ++q) {
        ulonglong2 xv = xr[q];
        acc[r] = ffma2(w[2 * q],     xv.x, acc[r]);
        acc[r] = ffma2(w[2 * q + 1], xv.y, acc[r]);
      }
    }

    float p[8];
    #pragma unroll
    for (int r = 0; r < 8; ++r) p[r] = hsum2(acc[r]);

    if (kh == 1) {
      #pragma unroll
      for (int r = 0; r < 8; ++r) sP[c & 1][r * 256 + j] = p[r];
    }
    if (c < 31 && tid < 256) {
      reinterpret_cast<float4*>(sX[(c + 1) & 1])[tid] = pf;
    }
    __syncthreads();
    if (kh == 0) {
      float* op = g_xproj + (rowbase + (size_t)c * 8) * HH + j;
      #pragma unroll
      for (int r = 0; r < 8; ++r) {
        op[r * HH] = p[r] + sP[c & 1][r * 256 + j];
      }
    }
  }
}

// ---------------------------------------------------------------------------
// Kernel 2: recurrence. 128 CTAs x 1024 threads (8 warps/SMSP), one CTA per
// batch pair. Thread (JQ = tid>>3 -> j in {2JQ, 2JQ+1}, KH = tid&7 -> k in
// [32KH, 32KH+32)). KH lives in LANE bits 0-2, so the 8-way k-reduction is
// IN-WARP: shfl_xor(1) scatters jsel, shfl_xor(2) scatters b, shfl_xor(4)
// folds the duplicate half. W: 32 floats/thread in regs + 32 via
// conflict-free spread LDS (fits 64-reg cap). h double-buffered in padded
// [8][36] smem. ONE barrier per step; KH<4 lanes finalize + store.
// ---------------------------------------------------------------------------
__global__ void __launch_bounds__(1024, 1) recurrence_kernel(
    const float* __restrict__ hx, const float* __restrict__ W_hh,
    const float* __restrict__ W_actor, const float* __restrict__ W_critic,
    float* __restrict__ out) {
  extern __shared__ float smem[];
  // sW: [ (q-4)*2 + jsel ][1024] ulonglong2 = 8*1024*16B = 131072B
  ulonglong2* sW = reinterpret_cast<ulonglong2*>(smem);
  float* shb = smem + 8 * 1024 * 4;  // [2 parity][2 b][288]

  const int tid = threadIdx.x;
  const int KH = tid & 7;
  const int JQ = tid >> 3;          // 0..127
  const int j0 = 2 * JQ;
  const int kb = KH * 32;
  const int b0g = blockIdx.x * 2;

  const int jf = j0 + (KH & 1);      // owned j (lanes KH and KH^4 duplicate)
  const int bf = (KH >> 1) & 1;      // owned batch

  // ---- stage W regs: q = 0..3 (k = kb .. kb+15), both j ----
  ull w0[8], w1[8];
  {
    const float4* wp0 = reinterpret_cast<const float4*>(W_hh + j0 * HH + kb);
    const float4* wp1 =
        reinterpret_cast<const float4*>(W_hh + (j0 + 1) * HH + kb);
    #pragma unroll
    for (int q = 0; q < 4; ++q) {
      float4 f0 = __ldg(wp0 + q);
      float4 f1 = __ldg(wp1 + q);
      w0[2 * q]     = pack2(f0.x, f0.y);
      w0[2 * q + 1] = pack2(f0.z, f0.w);
      w1[2 * q]     = pack2(f1.x, f1.y);
      w1[2 * q + 1] = pack2(f1.z, f1.w);
    }
  }
  // ---- stage W smem: q = 4..7 (k = kb+16 .. kb+31), both j ----
  #pragma unroll
  for (int q = 4; q < 8; ++q) {
    float4 f0 = __ldg(reinterpret_cast<const float4*>(W_hh + j0 * HH + kb) + q);
    float4 f1 =
        __ldg(reinterpret_cast<const float4*>(W_hh + (j0 + 1) * HH + kb) + q);
    ulonglong2 v0, v1;
    v0.x = pack2(f0.x, f0.y); v0.y = pack2(f0.z, f0.w);
    v1.x = pack2(f1.x, f1.y); v1.y = pack2(f1.z, f1.w);
    sW[((q - 4) * 2 + 0) * 1024 + tid] = v0;
    sW[((q - 4) * 2 + 1) * 1024 + tid] = v1;
  }

  // ---- init h (parity 0); h_old tracked by finalizing lanes ----
  float h_old = hx[(b0g + bf) * HH + jf];
  if (KH < 4) {
    shb[bf * 288 + (jf >> 5) * 36 + (jf & 31)] = h_old;
  }
  __syncthreads();

  const float* xqp = g_xproj + ((size_t)(b0g + bf) * TT) * HH + jf;
  float xq_cur = (KH < 4) ? __ldg(xqp) : 0.0f;

  for (int t = 0; t < TT; ++t) {
    const int rp = t & 1;
    float xq_nxt = 0.0f;
    if (KH < 4 && t + 1 < TT) xq_nxt = __ldg(xqp + (size_t)(t + 1) * HH);

    const float* hbase = shb + rp * 576;
    const ulonglong2* hp0 =
        reinterpret_cast<const ulonglong2*>(hbase + KH * 36);
    const ulonglong2* hp1 =
        reinterpret_cast<const ulonglong2*>(hbase + 288 + KH * 36);

    ull a00 = 0ull, a10 = 0ull, a01 = 0ull, a11 = 0ull;

    #pragma unroll
    for (int q = 0; q < 8; ++q) {
      ulonglong2 v0 = hp0[q];
      ulonglong2 v1 = hp1[q];
      ull wa0, wa1, wb0, wb1;
      if (q < 4) {
        wa0 = w0[2 * q]; wa1 = w0[2 * q + 1];
        wb0 = w1[2 * q]; wb1 = w1[2 * q + 1];
      } else {
        ulonglong2 sv0 = sW[((q - 4) * 2 + 0) * 1024 + tid];
        ulonglong2 sv1 = sW[((q - 4) * 2 + 1) * 1024 + tid];
        wa0 = sv0.x; wa1 = sv0.y;
        wb0 = sv1.x; wb1 = sv1.y;
      }
      a00 = ffma2(wa0, v0.x, a00);
      a10 = ffma2(wb0, v0.x, a10);
      a01 = ffma2(wa0, v1.x, a01);
      a11 = ffma2(wb0, v1.x, a11);
      a00 = ffma2(wa1, v0.y, a00);
      a10 = ffma2(wb1, v0.y, a10);
      a01 = ffma2(wa1, v1.y, a01);
      a11 = ffma2(wb1, v1.y, a11);
    }

    // ---- in-warp octet reduce-scatter (lane bits 0,1), fold bit 2 ----
    const bool s0 = (tid & 1), s1 = (tid & 2);
    // round 1: scatter jsel over bit 0
    ull k0, g0, k1, g1;
    k0 = s0 ? a10 : a00;  g0 = s0 ? a00 : a10;   // batch 0
    k1 = s0 ? a11 : a01;  g1 = s0 ? a01 : a11;   // batch 1
    k0 = add2(k0, __shfl_xor_sync(0xffffffffu, g0, 1));
    k1 = add2(k1, __shfl_xor_sync(0xffffffffu, g1, 1));
    // round 2: scatter batch over bit 1
    ull kk = s1 ? k1 : k0;
    ull gg = s1 ? k0 : k1;
    kk = add2(kk, __shfl_xor_sync(0xffffffffu, gg, 2));
    // round 3: fold duplicate half (bit 2)
    kk = add2(kk, __shfl_xor_sync(0xffffffffu, kk, 4));

    // ---- finalize owned (b, j): lanes KH<4 store ----
    if (KH < 4) {
      float p = hsum2(kk) + xq_cur;
      h_old = 0.8f * h_old + 0.2f * fmaxf(p, 0.0f);
      shb[(rp ^ 1) * 576 + bf * 288 + (jf >> 5) * 36 + (jf & 31)] = h_old;
    }
    xq_cur = xq_nxt;
    __syncthreads();
  }

  // -------- epilogue (final h in parity-0 buffer) --------
  const float* hf0 = shb;
  const float* hf1 = shb + 288;
  float* out_actor  = out;                 // [B][A]
  float* out_critic = out + BB * AA;       // [B]
  float* out_hx     = out + BB * AA + BB;  // [B][H]

  if (tid < HH) {
    int pj = (tid >> 5) * 36 + (tid & 31);
    out_hx[b0g * HH + tid]       = hf0[pj];
    out_hx[(b0g + 1) * HH + tid] = hf1[pj];
  }

  const int wid = tid >> 5, lane = tid & 31;
  if (wid < AA) {
    float pa0 = 0.f, pa1 = 0.f;
    for (int jj = lane; jj < HH; jj += 32) {
      int pj = (jj >> 5) * 36 + (jj & 31);
      float wa = W_actor[wid * HH + jj];
      pa0 += wa * hf0[pj];
      pa1 += wa * hf1[pj];
    }
    #pragma unroll
    for (int off = 16; off; off >>= 1) {
      pa0 += __shfl_down_sync(0xffffffffu, pa0, off);
      pa1 += __shfl_down_sync(0xffffffffu, pa1, off);
    }
    if (lane == 0) {
      out_actor[b0g * AA + wid]       = pa0;
      out_actor[(b0g + 1) * AA + wid] = pa1;
    }
  }
  if (wid == 8) {
    float pc0 = 0.f, pc1 = 0.f;
    for (int jj = lane; jj < HH; jj += 32) {
      int pj = (jj >> 5) * 36 + (jj & 31);
      float wc = W_critic[jj];
      pc0 += wc * hf0[pj];
      pc1 += wc * hf1[pj];
    }
    #pragma unroll
    for (int off = 16; off; off >>= 1) {
      pc0 += __shfl_down_sync(0xffffffffu, pc0, off);
      pc1 += __shfl_down_sync(0xffffffffu, pc1, off);
    }
    if (lane == 0) {
      out_critic[b0g]     = pc0;
      out_critic[b0g + 1] = pc1;
    }
  }
}

// ---------------------------------------------------------------------------
extern "C" void kernel_launch(void* const* d_in, const int* in_sizes, int n_in,
                              void* d_out, int out_size) {
  const float* x        = (const float*)d_in[0];
  const float* hx       = (const float*)d_in[1];
  const float* W_ih     = (const float*)d_in[2];
  const float* W_hh     = (const float*)d_in[3];
  const float* W_actor  = (const float*)d_in[4];
  const float* W_critic = (const float*)d_in[5];
  float* out = (float*)d_out;

  // smem: W 8*1024*16B = 131072B + h 2*2*288*4B = 4608B
  const int smem2 = 131072 + 4608;

  cudaFuncSetAttribute(recurrence_kernel,
                       cudaFuncAttributeMaxDynamicSharedMemorySize, smem2);

  xproj_kernel<<<(BB * TT) / 256, 512>>>(x, W_ih);
  recurrence_kernel<<<BB / 2, 1024, smem2>>>(hx, W_hh, W_actor, W_critic, out);
}